// round 16
// baseline (speedup 1.0000x reference)
#include <cuda_runtime.h>
#include <cuda_fp16.h>
#include <cstdint>

#define NTH     384
#define NPC     208               // 48-wide p chunks: 208*48 = 9984
#define TASKS   (128 * NPC * 2)   // (b, pc, wm) warp-tasks
#define PLEN    9984
#define LL      10000
#define NK      128

// smem: W 64KB (read-only after init) + per-warp double-buffered P (63 rows x 48B)
#define W_OFF   0
#define P_OFF   65536             // 12 warps x 2 x 3072B
#define SMEM_TOTAL (65536 + 12 * 6144)

static __device__ __forceinline__ uint32_t s2u(const void* p) {
    uint32_t a;
    asm("{ .reg .u64 t; cvta.to.shared.u64 t, %1; cvt.u32.u64 %0, t; }" : "=r"(a) : "l"(p));
    return a;
}

// Blocked SW128 atom layout for W [128 rows x 256 halves]; atom = 8 rows x 128B, rstride 16.
static __device__ __forceinline__ uint32_t wa(int row, int s) {
    uint32_t byte = (uint32_t)((((row >> 3) + ((s >> 6) << 4)) << 10) + ((row & 7) << 7) + ((s & 63) << 1));
    return byte ^ ((byte >> 3) & 0x70);
}
static __device__ __forceinline__ uint32_t wa_u(int row, int s) {
    return (uint32_t)((((row >> 3) + ((s >> 6) << 4)) << 10) + ((row & 7) << 7) + ((s & 63) << 1));
}

static __device__ __forceinline__ uint32_t f2h2(float a, float b) {
    __half2 h = __floats2half2_rn(a, b);
    return *reinterpret_cast<uint32_t*>(&h);
}

static __device__ __forceinline__ void ldsm4(uint32_t (&r)[4], uint32_t addr) {
    asm volatile("ldmatrix.sync.aligned.m8n8.x4.shared.b16 {%0,%1,%2,%3}, [%4];"
        : "=r"(r[0]), "=r"(r[1]), "=r"(r[2]), "=r"(r[3]) : "r"(addr));
}

static __device__ __forceinline__ void sts128(uint32_t addr, uint4 v) {
    asm volatile("st.shared.v4.b32 [%0], {%1,%2,%3,%4};"
        :: "r"(addr), "r"(v.x), "r"(v.y), "r"(v.z), "r"(v.w));
}

static __device__ __forceinline__ void mma16816(float (&d)[4], const uint32_t (&a)[4],
                                                uint32_t b0, uint32_t b1) {
    asm volatile("mma.sync.aligned.m16n8k16.row.col.f32.f16.f16.f32 "
        "{%0,%1,%2,%3}, {%4,%5,%6,%7}, {%8,%9}, {%0,%1,%2,%3};"
        : "+f"(d[0]), "+f"(d[1]), "+f"(d[2]), "+f"(d[3])
        : "r"(a[0]), "r"(a[1]), "r"(a[2]), "r"(a[3]), "r"(b0), "r"(b1));
}

// Build P row t from registers: P[t][c1*4+c2] = a[c1] * c[c2]; 32B at t*48.
static __device__ __forceinline__ void build_row(uint32_t pbase, int t, float4 a, float4 c) {
    uint4 lo, hi;
    lo.x = f2h2(a.x * c.x, a.x * c.y); lo.y = f2h2(a.x * c.z, a.x * c.w);
    lo.z = f2h2(a.y * c.x, a.y * c.y); lo.w = f2h2(a.y * c.z, a.y * c.w);
    hi.x = f2h2(a.z * c.x, a.z * c.y); hi.y = f2h2(a.z * c.z, a.z * c.w);
    hi.z = f2h2(a.w * c.x, a.w * c.y); hi.w = f2h2(a.w * c.z, a.w * c.w);
    sts128(pbase + t * 48, lo);
    sts128(pbase + t * 48 + 16, hi);
}

// exchange one float2 across shfl_xor(m)
static __device__ __forceinline__ void xpose_pair(float2& a, float2& b, int sel, int m) {
    float2 s = sel ? a : b;
    float2 r;
    r.x = __shfl_xor_sync(0xffffffffu, s.x, m);
    r.y = __shfl_xor_sync(0xffffffffu, s.y, m);
    if (sel) a = r; else b = r;
}

__global__ void __launch_bounds__(NTH, 1)
markonv_kernel(const float* __restrict__ x, const float* __restrict__ ker,
               float* __restrict__ out) {
    extern __shared__ char smem[];
    uint32_t sb = s2u(smem);
    const int tid = threadIdx.x;
    const int lane = tid & 31;
    const int wid = tid >> 5;

    // ---- stage W once (read-only afterwards): W'[k][s] = ker[s*128 + k] ----
    for (int idx = tid; idx < 128 * 128; idx += NTH) {
        int k = idx & 127, s = (idx >> 7) << 1;
        *(uint32_t*)(smem + W_OFF + wa(k, s)) =
            f2h2(ker[s * 128 + k], ker[s * 128 + 128 + k]);
    }
    __syncthreads();   // the ONLY block-wide barrier

    const uint32_t wsb = sb + W_OFF;
    const uint32_t mypbase = sb + P_OFF + wid * 6144;
    // B (P) lane addressing: rows in [0,16) + frag offset; per-kstep +48, +16 rows -> +768
    const uint32_t pblane_off = (uint32_t)(((lane & 7) + ((lane >> 4) << 3)) * 48
                                           + (((lane >> 3) & 1) << 4));
    const int wstride = gridDim.x * (NTH / 32);

    int n = 0;
    for (int w = blockIdx.x * (NTH / 32) + wid; w < TASKS; w += wstride, n++) {
        const int b = w / (NPC * 2);
        const int r = w - b * (NPC * 2);
        const int pc = r >> 1, wm = r & 1;
        const int p0 = pc * 48;

        // ---- build private P (rows 0..62) into buffer n&1 ----
        const uint32_t pb = mypbase + (n & 1) * 3072;
        const float4* xg = (const float4*)(x + ((size_t)b * LL + p0) * 4);
        {
            float4 a0 = xg[lane], c0 = xg[lane + 1];
            build_row(pb, lane, a0, c0);
            if (lane < 31) {
                float4 a1 = xg[32 + lane], c1 = xg[33 + lane];
                build_row(pb, 32 + lane, a1, c1);
            }
        }
        __syncwarp();

        // A (W) lane addressing for this wm half
        const int a_row = wm * 64 + (lane & 15);
        const uint32_t wbyteU = wa_u(a_row, (lane >> 4) << 3);
        const uint32_t wmask  = (uint32_t)((a_row & 7) << 4);
        const uint32_t pcur = pb + pblane_off;

        // ---- GEMM: D[64k x 48p] = W[wm] * V^T, V[p][16ks+cc] = P[p+ks][cc] ----
        float acc[4][6][4];
        #pragma unroll
        for (int mf = 0; mf < 4; mf++)
            #pragma unroll
            for (int nf = 0; nf < 6; nf++)
                #pragma unroll
                for (int e = 0; e < 4; e++) acc[mf][nf][e] = 0.f;

        #pragma unroll
        for (int ks = 0; ks < 16; ks++) {
            uint32_t af[4][4], bf[3][4];
            const uint32_t d = (uint32_t)((ks >> 2) * 16384 + (ks & 3) * 32);
            const uint32_t ab = wsb + ((wbyteU + d) ^ wmask);
            const uint32_t bb = pcur + (uint32_t)(ks * 48);
            ldsm4(af[0], ab);
            ldsm4(af[1], ab + 2048);
            ldsm4(af[2], ab + 4096);
            ldsm4(af[3], ab + 6144);
            ldsm4(bf[0], bb);
            ldsm4(bf[1], bb + 768);
            ldsm4(bf[2], bb + 1536);
            #pragma unroll
            for (int j = 0; j < 3; j++)
                #pragma unroll
                for (int mf = 0; mf < 4; mf++) {
                    mma16816(acc[mf][2 * j],     af[mf], bf[j][0], bf[j][1]);
                    mma16816(acc[mf][2 * j + 1], af[mf], bf[j][2], bf[j][3]);
                }
        }

        // ---- epilogue: nf0-3 quad 4x4 transpose (2x STG.128); nf4-5 2x2 (1x STG.128) ----
        {
            const size_t obase = ((size_t)b * NK + wm * 64) * PLEN + p0;
            const int q = lane & 3;
            const int krow = lane >> 2;
            #pragma unroll
            for (int mf = 0; mf < 4; mf++) {
                #pragma unroll
                for (int h = 0; h < 2; h++) {
                    const size_t orow = obase + (size_t)(mf * 16 + krow + 8 * h) * PLEN;
                    // group A: nf 0..3 -> p 0..31
                    {
                        float2 v0 = make_float2(acc[mf][0][2*h], acc[mf][0][2*h+1]);
                        float2 v1 = make_float2(acc[mf][1][2*h], acc[mf][1][2*h+1]);
                        float2 v2 = make_float2(acc[mf][2][2*h], acc[mf][2][2*h+1]);
                        float2 v3 = make_float2(acc[mf][3][2*h], acc[mf][3][2*h+1]);
                        xpose_pair(v0, v1, q & 1, 1);
                        xpose_pair(v2, v3, q & 1, 1);
                        xpose_pair(v0, v2, q & 2, 2);
                        xpose_pair(v1, v3, q & 2, 2);
                        *(float4*)(out + orow + q * 8)     = make_float4(v0.x, v0.y, v1.x, v1.y);
                        *(float4*)(out + orow + q * 8 + 4) = make_float4(v2.x, v2.y, v3.x, v3.y);
                    }
                    // group B: nf 4..5 -> p 32..47, one xor1 exchange
                    {
                        float2 v4 = make_float2(acc[mf][4][2*h], acc[mf][4][2*h+1]);
                        float2 v5 = make_float2(acc[mf][5][2*h], acc[mf][5][2*h+1]);
                        xpose_pair(v4, v5, q & 1, 1);
                        const int pofs = 32 + ((q & 1) << 3) + ((q & 2) << 1);
                        *(float4*)(out + orow + pofs) = make_float4(v4.x, v4.y, v5.x, v5.y);
                    }
                }
            }
        }
    }
}

extern "C" void kernel_launch(void* const* d_in, const int* in_sizes, int n_in,
                              void* d_out, int out_size) {
    static int nsm = 0;
    if (nsm == 0) {
        int dev = 0;
        cudaGetDevice(&dev);
        if (cudaDeviceGetAttribute(&nsm, cudaDevAttrMultiProcessorCount, dev) != cudaSuccess || nsm <= 0)
            nsm = 148;
        cudaFuncSetAttribute(markonv_kernel, cudaFuncAttributeMaxDynamicSharedMemorySize, SMEM_TOTAL);
    }
    markonv_kernel<<<nsm, NTH, SMEM_TOTAL>>>(
        (const float*)d_in[0], (const float*)d_in[1], (float*)d_out);
}

// round 17
// speedup vs baseline: 1.1431x; 1.1431x over previous
#include <cuda_runtime.h>
#include <cuda_fp16.h>
#include <cstdint>

#define NTH     512
#define NPC     312               // 32-wide p chunks: 312*32 = 9984
#define TASKS   (128 * NPC * 2)   // (b, pc, wm) warp-tasks
#define PLEN    9984
#define LL      10000
#define NK      128

// smem: W 64KB (read-only after init) + per-warp double-buffered P
#define W_OFF   0
#define P_OFF   65536             // 16 warps x 2 x 2304B
#define SMEM_TOTAL (65536 + 16 * 4608)

static __device__ __forceinline__ uint32_t s2u(const void* p) {
    uint32_t a;
    asm("{ .reg .u64 t; cvta.to.shared.u64 t, %1; cvt.u32.u64 %0, t; }" : "=r"(a) : "l"(p));
    return a;
}

// Blocked SW128 atom layout for W [128 rows x 256 halves]; atom = 8 rows x 128B, rstride 16.
static __device__ __forceinline__ uint32_t wa(int row, int s) {
    uint32_t byte = (uint32_t)((((row >> 3) + ((s >> 6) << 4)) << 10) + ((row & 7) << 7) + ((s & 63) << 1));
    return byte ^ ((byte >> 3) & 0x70);
}
static __device__ __forceinline__ uint32_t wa_u(int row, int s) {
    return (uint32_t)((((row >> 3) + ((s >> 6) << 4)) << 10) + ((row & 7) << 7) + ((s & 63) << 1));
}

static __device__ __forceinline__ uint32_t f2h2(float a, float b) {
    __half2 h = __floats2half2_rn(a, b);
    return *reinterpret_cast<uint32_t*>(&h);
}

static __device__ __forceinline__ void ldsm4(uint32_t (&r)[4], uint32_t addr) {
    asm volatile("ldmatrix.sync.aligned.m8n8.x4.shared.b16 {%0,%1,%2,%3}, [%4];"
        : "=r"(r[0]), "=r"(r[1]), "=r"(r[2]), "=r"(r[3]) : "r"(addr));
}

static __device__ __forceinline__ void sts128(uint32_t addr, uint4 v) {
    asm volatile("st.shared.v4.b32 [%0], {%1,%2,%3,%4};"
        :: "r"(addr), "r"(v.x), "r"(v.y), "r"(v.z), "r"(v.w));
}

static __device__ __forceinline__ void mma16816(float (&d)[4], const uint32_t (&a)[4],
                                                uint32_t b0, uint32_t b1) {
    asm volatile("mma.sync.aligned.m16n8k16.row.col.f32.f16.f16.f32 "
        "{%0,%1,%2,%3}, {%4,%5,%6,%7}, {%8,%9}, {%0,%1,%2,%3};"
        : "+f"(d[0]), "+f"(d[1]), "+f"(d[2]), "+f"(d[3])
        : "r"(a[0]), "r"(a[1]), "r"(a[2]), "r"(a[3]), "r"(b0), "r"(b1));
}

// Build P row t from registers: P[t][c1*4+c2] = a[c1] * c[c2]; 32B at t*48.
static __device__ __forceinline__ void build_row(uint32_t pbase, int t, float4 a, float4 c) {
    uint4 lo, hi;
    lo.x = f2h2(a.x * c.x, a.x * c.y); lo.y = f2h2(a.x * c.z, a.x * c.w);
    lo.z = f2h2(a.y * c.x, a.y * c.y); lo.w = f2h2(a.y * c.z, a.y * c.w);
    hi.x = f2h2(a.z * c.x, a.z * c.y); hi.y = f2h2(a.z * c.z, a.z * c.w);
    hi.z = f2h2(a.w * c.x, a.w * c.y); hi.w = f2h2(a.w * c.z, a.w * c.w);
    sts128(pbase + t * 48, lo);
    sts128(pbase + t * 48 + 16, hi);
}

// exchange one float2 across shfl_xor(m)
static __device__ __forceinline__ void xpose_pair(float2& a, float2& b, int sel, int m) {
    float2 s = sel ? a : b;
    float2 r;
    r.x = __shfl_xor_sync(0xffffffffu, s.x, m);
    r.y = __shfl_xor_sync(0xffffffffu, s.y, m);
    if (sel) a = r; else b = r;
}

__global__ void __launch_bounds__(NTH, 1)
markonv_kernel(const float* __restrict__ x, const float* __restrict__ ker,
               float* __restrict__ out) {
    extern __shared__ char smem[];
    uint32_t sb = s2u(smem);
    const int tid = threadIdx.x;
    const int lane = tid & 31;
    const int wid = tid >> 5;

    // ---- stage W once (read-only afterwards): W'[k][s] = ker[s*128 + k] ----
    for (int idx = tid; idx < 128 * 128; idx += NTH) {
        int k = idx & 127, s = (idx >> 7) << 1;
        *(uint32_t*)(smem + W_OFF + wa(k, s)) =
            f2h2(ker[s * 128 + k], ker[s * 128 + 128 + k]);
    }
    __syncthreads();   // the ONLY block-wide barrier

    const uint32_t wsb = sb + W_OFF;
    const uint32_t mypbase = sb + P_OFF + wid * 4608;
    // B (P) lane addressing: rows in [0,16) + frag offset; per-kstep +48, +16 rows -> +768
    const uint32_t pblane_off = (uint32_t)(((lane & 7) + ((lane >> 4) << 3)) * 48
                                           + (((lane >> 3) & 1) << 4));
    const int wstride = gridDim.x * (NTH / 32);

    int n = 0;
    for (int w = blockIdx.x * (NTH / 32) + wid; w < TASKS; w += wstride, n++) {
        const int b = w / (NPC * 2);
        const int r = w - b * (NPC * 2);
        const int pc = r >> 1, wm = r & 1;
        const int p0 = pc * 32;

        // ---- build private P (rows 0..46) into buffer n&1 ----
        const uint32_t pb = mypbase + (n & 1) * 2304;
        const float4* xg = (const float4*)(x + ((size_t)b * LL + p0) * 4);
        {
            float4 a0 = xg[lane], c0 = xg[lane + 1];
            build_row(pb, lane, a0, c0);
            if (lane < 15) {
                float4 a1 = xg[32 + lane], c1 = xg[33 + lane];
                build_row(pb, 32 + lane, a1, c1);
            }
        }
        __syncwarp();

        // A (W) lane addressing for this wm half
        const int a_row = wm * 64 + (lane & 15);
        const uint32_t wbyteU = wa_u(a_row, (lane >> 4) << 3);
        const uint32_t wmask  = (uint32_t)((a_row & 7) << 4);
        const uint32_t pcur = pb + pblane_off;

        // ---- GEMM: D[64k x 32p] = W[wm] * V^T, V[p][16ks+cc] = P[p+ks][cc] ----
        float acc[4][4][4];
        #pragma unroll
        for (int mf = 0; mf < 4; mf++)
            #pragma unroll
            for (int nf = 0; nf < 4; nf++)
                #pragma unroll
                for (int e = 0; e < 4; e++) acc[mf][nf][e] = 0.f;

        #pragma unroll
        for (int ks = 0; ks < 16; ks++) {
            uint32_t af[4][4], bf[2][4];
            const uint32_t d = (uint32_t)((ks >> 2) * 16384 + (ks & 3) * 32);
            const uint32_t ab = wsb + ((wbyteU + d) ^ wmask);
            const uint32_t bb = pcur + (uint32_t)(ks * 48);
            ldsm4(af[0], ab);
            ldsm4(af[1], ab + 2048);
            ldsm4(af[2], ab + 4096);
            ldsm4(af[3], ab + 6144);
            ldsm4(bf[0], bb);
            ldsm4(bf[1], bb + 768);
            #pragma unroll
            for (int mf = 0; mf < 4; mf++) {
                mma16816(acc[mf][0], af[mf], bf[0][0], bf[0][1]);
                mma16816(acc[mf][1], af[mf], bf[0][2], bf[0][3]);
                mma16816(acc[mf][2], af[mf], bf[1][0], bf[1][1]);
                mma16816(acc[mf][3], af[mf], bf[1][2], bf[1][3]);
            }
        }

        // ---- epilogue: quad 4x4 transpose + xor16 half-swap -> full-line STG.128 ----
        {
            const size_t obase = ((size_t)b * NK + wm * 64) * PLEN + p0;
            const int q = lane & 3;
            const int krow = lane >> 2;
            const int hi = (lane >> 4) & 1;     // krow >= 4
            #pragma unroll
            for (int mf = 0; mf < 4; mf++) {
                #pragma unroll
                for (int h = 0; h < 2; h++) {
                    float2 v0 = make_float2(acc[mf][0][2*h], acc[mf][0][2*h+1]);
                    float2 v1 = make_float2(acc[mf][1][2*h], acc[mf][1][2*h+1]);
                    float2 v2 = make_float2(acc[mf][2][2*h], acc[mf][2][2*h+1]);
                    float2 v3 = make_float2(acc[mf][3][2*h], acc[mf][3][2*h+1]);
                    // stages 1+2: quad 4x4 transpose -> lane holds p=8q..8q+7 of row krow
                    xpose_pair(v0, v1, q & 1, 1);
                    xpose_pair(v2, v3, q & 1, 1);
                    xpose_pair(v0, v2, q & 2, 2);
                    xpose_pair(v1, v3, q & 2, 2);
                    // stage 3: swap (v2,v3) across lane^16 (rows krow <-> krow+4)
                    float4 rec;
                    rec.x = __shfl_xor_sync(0xffffffffu, v2.x, 16);
                    rec.y = __shfl_xor_sync(0xffffffffu, v2.y, 16);
                    rec.z = __shfl_xor_sync(0xffffffffu, v3.x, 16);
                    rec.w = __shfl_xor_sync(0xffffffffu, v3.y, 16);
                    const float4 own = make_float4(v0.x, v0.y, v1.x, v1.y);
                    const int rbase = mf * 16 + (krow & 3) + 8 * h;
                    // instr 1: rows rbase (0..3 block), full 128B line per row
                    {
                        const float4 val = hi ? rec : own;
                        const int col = q * 8 + (hi ? 4 : 0);
                        *(float4*)(out + obase + (size_t)rbase * PLEN + col) = val;
                    }
                    // instr 2: rows rbase+4, complementary halves
                    {
                        const float4 val = hi ? own : rec;
                        const int col = q * 8 + (hi ? 0 : 4);
                        *(float4*)(out + obase + (size_t)(rbase + 4) * PLEN + col) = val;
                    }
                }
            }
        }
    }
}

extern "C" void kernel_launch(void* const* d_in, const int* in_sizes, int n_in,
                              void* d_out, int out_size) {
    static int nsm = 0;
    if (nsm == 0) {
        int dev = 0;
        cudaGetDevice(&dev);
        if (cudaDeviceGetAttribute(&nsm, cudaDevAttrMultiProcessorCount, dev) != cudaSuccess || nsm <= 0)
            nsm = 148;
        cudaFuncSetAttribute(markonv_kernel, cudaFuncAttributeMaxDynamicSharedMemorySize, SMEM_TOTAL);
    }
    markonv_kernel<<<nsm, NTH, SMEM_TOTAL>>>(
        (const float*)d_in[0], (const float*)d_in[1], (float*)d_out);
}